// round 3
// baseline (speedup 1.0000x reference)
#include <cuda_runtime.h>
#include <math.h>

// ---------------------------------------------------------------------------
// Problem: p = 4096 (square fp32 matrices).
//   s       = sum(target^2)                       (scalar)
//   W[i]    = sum_j W_beta[i,j]
//   scale_i = W_i^2 / (s*W_i^2 + 1)
//   G       = source @ target^T        (NT gemm)
//   Wm      = scale[:,None] * G                    -> output matrix
//   primary = Wm @ target - source     (NN gemm)
//   Z       = W_beta @ primary         (NN gemm, never materialized)
//   loss    = sqrt(sum(Z^2))                       -> output scalar
// ---------------------------------------------------------------------------

#define PMAX 4096
// Scratch (allocation-free rule: __device__ globals)
__device__ float  g_Wm[(size_t)PMAX * PMAX]; // aligned copy of W_matrix
__device__ float  g_Pr[(size_t)PMAX * PMAX]; // primary
__device__ float  g_W[PMAX];                 // row sums of W_beta
__device__ double g_s;                       // sum(target^2)
__device__ double g_ss;                      // sum(Z^2)

__global__ void init_kernel() { g_s = 0.0; g_ss = 0.0; }

__device__ __forceinline__ float blockReduceSum(float v) {
    __shared__ float sh[32];
    int lane = threadIdx.x & 31;
    int wid  = threadIdx.x >> 5;
#pragma unroll
    for (int o = 16; o; o >>= 1) v += __shfl_down_sync(0xffffffffu, v, o);
    if (lane == 0) sh[wid] = v;
    __syncthreads();
    int nw = (blockDim.x + 31) >> 5;
    v = (threadIdx.x < nw) ? sh[threadIdx.x] : 0.0f;
    if (wid == 0) {
#pragma unroll
        for (int o = 16; o; o >>= 1) v += __shfl_down_sync(0xffffffffu, v, o);
    }
    return v; // valid in thread 0
}

__global__ void sumsq_kernel(const float* __restrict__ X, size_t n) {
    float local = 0.0f;
    for (size_t i = (size_t)blockIdx.x * blockDim.x + threadIdx.x; i < n;
         i += (size_t)gridDim.x * blockDim.x) {
        float v = X[i];
        local += v * v;
    }
    float b = blockReduceSum(local);
    if (threadIdx.x == 0) atomicAdd(&g_s, (double)b);
}

__global__ void rowsum_kernel(const float* __restrict__ Wb, int P) {
    int row = blockIdx.x;
    const float* r = Wb + (size_t)row * P;
    float local = 0.0f;
    for (int j = threadIdx.x; j < P; j += blockDim.x) local += r[j];
    float b = blockReduceSum(local);
    if (threadIdx.x == 0) g_W[row] = b;
}

// ---------------------------------------------------------------------------
// GEMM tiles: 128x128 block tile, BK=8, 256 threads (16x16), 8x8 per thread.
// ---------------------------------------------------------------------------

// C[i,j] = sum_k A[i,k]*B[j,k]  (both row-major, "NT").
// Epilogue: Wm[i,j] = scale_i * C[i,j]; write to g_Wm (aligned) and optionally
// Cout (possibly misaligned base -> scalar stores).
__global__ __launch_bounds__(256) void gemm_nt_scale(
    const float* __restrict__ A, const float* __restrict__ B,
    float* __restrict__ Cout, int P)
{
    __shared__ float As[8][128];
    __shared__ float Bs[8][128];
    const int tid = threadIdx.x;
    const int tx = tid & 15, ty = tid >> 4;
    const int by = blockIdx.y, bx = blockIdx.x;

    const float* Ab = A + (size_t)(by * 128) * P;
    const float* Bb = B + (size_t)(bx * 128) * P;

    const int lrow = tid >> 1;
    const int lk   = (tid & 1) * 4;

    float acc[8][8];
#pragma unroll
    for (int i = 0; i < 8; i++)
#pragma unroll
        for (int j = 0; j < 8; j++) acc[i][j] = 0.0f;

    for (int k0 = 0; k0 < P; k0 += 8) {
        float4 a4 = *(const float4*)(Ab + (size_t)lrow * P + k0 + lk);
        float4 b4 = *(const float4*)(Bb + (size_t)lrow * P + k0 + lk);
        As[lk + 0][lrow] = a4.x; As[lk + 1][lrow] = a4.y;
        As[lk + 2][lrow] = a4.z; As[lk + 3][lrow] = a4.w;
        Bs[lk + 0][lrow] = b4.x; Bs[lk + 1][lrow] = b4.y;
        Bs[lk + 2][lrow] = b4.z; Bs[lk + 3][lrow] = b4.w;
        __syncthreads();
#pragma unroll
        for (int k = 0; k < 8; k++) {
            float a[8], b[8];
            *(float4*)&a[0] = *(const float4*)&As[k][ty * 8];
            *(float4*)&a[4] = *(const float4*)&As[k][ty * 8 + 4];
            *(float4*)&b[0] = *(const float4*)&Bs[k][tx * 8];
            *(float4*)&b[4] = *(const float4*)&Bs[k][tx * 8 + 4];
#pragma unroll
            for (int i = 0; i < 8; i++)
#pragma unroll
                for (int j = 0; j < 8; j++)
                    acc[i][j] = fmaf(a[i], b[j], acc[i][j]);
        }
        __syncthreads();
    }

    const double sd = g_s;
    const int gj = bx * 128 + tx * 8;
#pragma unroll
    for (int i = 0; i < 8; i++) {
        const int gi = by * 128 + ty * 8 + i;
        double w  = (double)g_W[gi];
        double w2 = w * w;
        float sc = (float)(w2 / (sd * w2 + 1.0));
        float r[8];
#pragma unroll
        for (int j = 0; j < 8; j++) r[j] = sc * acc[i][j];
        float* crow = g_Wm + (size_t)gi * P + gj;
        *(float4*)(crow)     = make_float4(r[0], r[1], r[2], r[3]);
        *(float4*)(crow + 4) = make_float4(r[4], r[5], r[6], r[7]);
        if (Cout) {
            float* orow = Cout + (size_t)gi * P + gj;
#pragma unroll
            for (int j = 0; j < 8; j++) orow[j] = r[j];
        }
    }
}

// primary = g_Wm @ B - Y   ("NN": C[i,j] = sum_k Wm[i,k]*B[k,j] - Y[i,j])
__global__ __launch_bounds__(256) void gemm_nn_sub(
    const float* __restrict__ B, const float* __restrict__ Y, int P)
{
    __shared__ float As[8][128];
    __shared__ float Bs[8][128];
    const int tid = threadIdx.x;
    const int tx = tid & 15, ty = tid >> 4;
    const int by = blockIdx.y, bx = blockIdx.x;

    const float* Ab = g_Wm + (size_t)(by * 128) * P;

    const int lrow = tid >> 1;          // A-tile load row (0..127)
    const int lk   = (tid & 1) * 4;     // A-tile k group
    const int brow = tid >> 5;          // B-tile k row (0..7)
    const int bcol = (tid & 31) * 4;    // B-tile col group

    float acc[8][8];
#pragma unroll
    for (int i = 0; i < 8; i++)
#pragma unroll
        for (int j = 0; j < 8; j++) acc[i][j] = 0.0f;

    for (int k0 = 0; k0 < P; k0 += 8) {
        float4 a4 = *(const float4*)(Ab + (size_t)lrow * P + k0 + lk);
        float4 b4 = *(const float4*)(B + (size_t)(k0 + brow) * P + bx * 128 + bcol);
        As[lk + 0][lrow] = a4.x; As[lk + 1][lrow] = a4.y;
        As[lk + 2][lrow] = a4.z; As[lk + 3][lrow] = a4.w;
        *(float4*)&Bs[brow][bcol] = b4;
        __syncthreads();
#pragma unroll
        for (int k = 0; k < 8; k++) {
            float a[8], b[8];
            *(float4*)&a[0] = *(const float4*)&As[k][ty * 8];
            *(float4*)&a[4] = *(const float4*)&As[k][ty * 8 + 4];
            *(float4*)&b[0] = *(const float4*)&Bs[k][tx * 8];
            *(float4*)&b[4] = *(const float4*)&Bs[k][tx * 8 + 4];
#pragma unroll
            for (int i = 0; i < 8; i++)
#pragma unroll
                for (int j = 0; j < 8; j++)
                    acc[i][j] = fmaf(a[i], b[j], acc[i][j]);
        }
        __syncthreads();
    }

    const int gj = bx * 128 + tx * 8;
#pragma unroll
    for (int i = 0; i < 8; i++) {
        const int gi = by * 128 + ty * 8 + i;
        const float* yrow = Y + (size_t)gi * P + gj;
        float4 y0 = *(const float4*)(yrow);
        float4 y1 = *(const float4*)(yrow + 4);
        float* crow = g_Pr + (size_t)gi * P + gj;
        *(float4*)(crow) = make_float4(acc[i][0] - y0.x, acc[i][1] - y0.y,
                                       acc[i][2] - y0.z, acc[i][3] - y0.w);
        *(float4*)(crow + 4) = make_float4(acc[i][4] - y1.x, acc[i][5] - y1.y,
                                           acc[i][6] - y1.z, acc[i][7] - y1.w);
    }
}

// Z = A @ g_Pr ("NN"); accumulate sum(Z^2) into g_ss; Z never stored.
__global__ __launch_bounds__(256) void gemm_nn_ssq(
    const float* __restrict__ A, int P)
{
    __shared__ float As[8][128];
    __shared__ float Bs[8][128];
    const int tid = threadIdx.x;
    const int tx = tid & 15, ty = tid >> 4;
    const int by = blockIdx.y, bx = blockIdx.x;

    const float* Ab = A + (size_t)(by * 128) * P;

    const int lrow = tid >> 1;
    const int lk   = (tid & 1) * 4;
    const int brow = tid >> 5;
    const int bcol = (tid & 31) * 4;

    float acc[8][8];
#pragma unroll
    for (int i = 0; i < 8; i++)
#pragma unroll
        for (int j = 0; j < 8; j++) acc[i][j] = 0.0f;

    for (int k0 = 0; k0 < P; k0 += 8) {
        float4 a4 = *(const float4*)(Ab + (size_t)lrow * P + k0 + lk);
        float4 b4 = *(const float4*)(g_Pr + (size_t)(k0 + brow) * P + bx * 128 + bcol);
        As[lk + 0][lrow] = a4.x; As[lk + 1][lrow] = a4.y;
        As[lk + 2][lrow] = a4.z; As[lk + 3][lrow] = a4.w;
        *(float4*)&Bs[brow][bcol] = b4;
        __syncthreads();
#pragma unroll
        for (int k = 0; k < 8; k++) {
            float a[8], b[8];
            *(float4*)&a[0] = *(const float4*)&As[k][ty * 8];
            *(float4*)&a[4] = *(const float4*)&As[k][ty * 8 + 4];
            *(float4*)&b[0] = *(const float4*)&Bs[k][tx * 8];
            *(float4*)&b[4] = *(const float4*)&Bs[k][tx * 8 + 4];
#pragma unroll
            for (int i = 0; i < 8; i++)
#pragma unroll
                for (int j = 0; j < 8; j++)
                    acc[i][j] = fmaf(a[i], b[j], acc[i][j]);
        }
        __syncthreads();
    }

    float local = 0.0f;
#pragma unroll
    for (int i = 0; i < 8; i++)
#pragma unroll
        for (int j = 0; j < 8; j++) local += acc[i][j] * acc[i][j];
    float b = blockReduceSum(local);
    if (threadIdx.x == 0) atomicAdd(&g_ss, (double)b);
}

__global__ void finalize_kernel(float* __restrict__ out) {
    out[0] = (float)sqrt(g_ss);
}

extern "C" void kernel_launch(void* const* d_in, const int* in_sizes, int n_in,
                              void* d_out, int out_size)
{
    const float* target = (const float*)d_in[0];
    const float* source = (const float*)d_in[1];
    const float* Wb     = (const float*)d_in[2];
    float* out = (float*)d_out;

    // p from element count (p*p elements)
    int P = (int)(sqrt((double)in_sizes[0]) + 0.5);
    size_t pp = (size_t)P * P;

    // Output layout: tuple (loss, W_matrix) flattened -> loss first, then matrix.
    bool has_matrix = (size_t)out_size >= pp;
    bool has_loss   = ((size_t)out_size != pp);
    float* outW = has_matrix ? (out + (out_size - (int)pp)) : nullptr;

    init_kernel<<<1, 1>>>();
    sumsq_kernel<<<2048, 256>>>(target, pp);
    rowsum_kernel<<<P, 256>>>(Wb, P);

    dim3 grid(P / 128, P / 128);
    gemm_nt_scale<<<grid, 256>>>(source, target, outW, P);
    gemm_nn_sub<<<grid, 256>>>(target, source, P);
    gemm_nn_ssq<<<grid, 256>>>(Wb, P);

    if (has_loss) finalize_kernel<<<1, 1>>>(out);
}

// round 5
// speedup vs baseline: 2.8992x; 2.8992x over previous
#include <cuda_runtime.h>
#include <cuda_bf16.h>
#include <math.h>
#include <stdint.h>

// ---------------------------------------------------------------------------
//   s       = sum(target^2);  W[i] = rowsum(W_beta);  scale_i = W^2/(s W^2+1)
//   G       = source @ target^T          -> Wm = scale[:,None]*G  (GEMM 1)
//   primary = Wm @ target - source       (GEMM 2, B = pre-transposed target,
//                                         result stored transposed)
//   loss    = sqrt(||W_beta @ primary||^2)  (GEMM 3, Z never stored)
// GEMMs: D[m,n] = sum_k A[m,k]*B[n,k], K-major operands, bf16x3 split on
// mma.sync.m16n8k16 (sm_80 base ISA -- tcgen05 is unavailable: harness
// compiles to compute_103 without the 'a' suffix).
// ---------------------------------------------------------------------------

#define PMAX 4096
__device__ float  g_Wm [(size_t)PMAX * PMAX];
__device__ float  g_PrT[(size_t)PMAX * PMAX];
__device__ float  g_Tt [(size_t)PMAX * PMAX];
__device__ float  g_W[PMAX];
__device__ double g_s;
__device__ double g_ss;

__device__ __forceinline__ uint32_t smem_u32(const void* p) {
    uint32_t a;
    asm("{ .reg .u64 t; cvta.to.shared.u64 t, %1; cvt.u32.u64 %0, t; }"
        : "=r"(a) : "l"(p));
    return a;
}

__device__ __forceinline__ void ldsm4(uint32_t* r, uint32_t addr) {
    asm volatile("ldmatrix.sync.aligned.m8n8.x4.shared.b16 {%0,%1,%2,%3}, [%4];"
        : "=r"(r[0]), "=r"(r[1]), "=r"(r[2]), "=r"(r[3]) : "r"(addr));
}

__device__ __forceinline__ void mma_bf16(float* c, const uint32_t* a,
                                         const uint32_t* b) {
    asm volatile(
        "mma.sync.aligned.m16n8k16.row.col.f32.bf16.bf16.f32 "
        "{%0,%1,%2,%3}, {%4,%5,%6,%7}, {%8,%9}, {%0,%1,%2,%3};"
        : "+f"(c[0]), "+f"(c[1]), "+f"(c[2]), "+f"(c[3])
        : "r"(a[0]), "r"(a[1]), "r"(a[2]), "r"(a[3]), "r"(b[0]), "r"(b[1]));
}

__device__ __forceinline__ void split2(float x, float y, uint32_t& h, uint32_t& l) {
    __nv_bfloat162 hp = __floats2bfloat162_rn(x, y);   // .x = bf16(x) (low half)
    float rx = x - __low2float(hp);
    float ry = y - __high2float(hp);
    __nv_bfloat162 lp = __floats2bfloat162_rn(rx, ry);
    h = *reinterpret_cast<uint32_t*>(&hp);
    l = *reinterpret_cast<uint32_t*>(&lp);
}

#define STS64(addr, r0, r1) \
    asm volatile("st.shared.v2.b32 [%0], {%1,%2};" \
        :: "r"(addr), "r"(r0), "r"(r1) : "memory")

// ---------------- small kernels ------------------------------------------
__global__ void init_kernel() { g_s = 0.0; g_ss = 0.0; }

__device__ __forceinline__ float blockReduceSum(float v) {
    __shared__ float sh[32];
    int lane = threadIdx.x & 31, wid = threadIdx.x >> 5;
#pragma unroll
    for (int o = 16; o; o >>= 1) v += __shfl_down_sync(0xffffffffu, v, o);
    if (lane == 0) sh[wid] = v;
    __syncthreads();
    int nw = (blockDim.x + 31) >> 5;
    v = (threadIdx.x < nw) ? sh[threadIdx.x] : 0.0f;
    if (wid == 0)
#pragma unroll
        for (int o = 16; o; o >>= 1) v += __shfl_down_sync(0xffffffffu, v, o);
    return v;
}

__global__ void sumsq_kernel(const float* __restrict__ X, size_t n) {
    float local = 0.0f;
    for (size_t i = (size_t)blockIdx.x * blockDim.x + threadIdx.x; i < n;
         i += (size_t)gridDim.x * blockDim.x) {
        float v = X[i];
        local += v * v;
    }
    float b = blockReduceSum(local);
    if (threadIdx.x == 0) atomicAdd(&g_s, (double)b);
}

__global__ void rowsum_kernel(const float* __restrict__ Wb, int P) {
    const float* r = Wb + (size_t)blockIdx.x * P;
    float local = 0.0f;
    for (int j = threadIdx.x; j < P; j += blockDim.x) local += r[j];
    float b = blockReduceSum(local);
    if (threadIdx.x == 0) g_W[blockIdx.x] = b;
}

__global__ void transpose_kernel(const float* __restrict__ in,
                                 float* __restrict__ out, int P) {
    __shared__ float tile[32][33];
    int tx = threadIdx.x, ty = threadIdx.y;
    int x = blockIdx.x * 32 + tx;
    int y0 = blockIdx.y * 32;
#pragma unroll
    for (int j = 0; j < 32; j += 8)
        tile[ty + j][tx] = in[(size_t)(y0 + ty + j) * P + x];
    __syncthreads();
    int xo = blockIdx.y * 32 + tx;
    int yo0 = blockIdx.x * 32;
#pragma unroll
    for (int j = 0; j < 32; j += 8)
        out[(size_t)(yo0 + ty + j) * P + xo] = tile[tx][ty + j];
}

__global__ void finalize_kernel(float* __restrict__ out) {
    out[0] = (float)sqrt(g_ss);
}

// ---------------- mma.sync GEMM ------------------------------------------
// Block 128x128, BK=32, 256 threads = 8 warps in 4(M) x 2(N); warp tile 32x64.
// SMEM stage: Ahi|Alo|Bhi|Blo, each 128 rows x 40 bf16 (80B padded) = 10240B.
#define BM 128
#define BN 128
#define BK 32
#define ROWB 80
#define TILEB (128 * ROWB)     // 10240
#define STAGEB (4 * TILEB)     // 40960
#define SMEM_SZ (2 * STAGEB)   // 81920 (epilogue staging overlays this)

// MODE 1: D *= scale[row]; -> O0 (g_Wm) + optional O1 (d_out, maybe unaligned)
// MODE 2: D -= aux;  store transposed -> O0 (g_PrT)
// MODE 3: g_ss += sum(D^2)
template <int MODE>
__global__ __launch_bounds__(256, 1) void gemm_mma(
    const float* __restrict__ A, const float* __restrict__ B,
    const float* __restrict__ aux, float* __restrict__ O0,
    float* __restrict__ O1, int P)
{
    extern __shared__ char smraw[];
    const uint32_t sb = smem_u32(smraw);

    const int tid = threadIdx.x, lane = tid & 31, wid = tid >> 5;
    const int wm = wid >> 1, wn = wid & 1;
    const int bx = blockIdx.x, by = blockIdx.y;

    const float* Ab = A + (size_t)(by * BM) * P;
    const float* Bb = B + (size_t)(bx * BN) * P;
    const int iters = P / BK;

    float acc[2][8][4];
#pragma unroll
    for (int mt = 0; mt < 2; mt++)
#pragma unroll
        for (int nt = 0; nt < 8; nt++)
#pragma unroll
            for (int i = 0; i < 4; i++) acc[mt][nt][i] = 0.0f;

    const int lrow = tid >> 3;     // base row (0..31), +32*i
    const int lkg  = tid & 7;      // k-group (float4 index)

    // ldmatrix source addresses (per warp, fixed across iters except stage base)
    //   A frags: lanes 0-15 rows r0..r0+15 @k0 ; lanes 16-31 same rows @k0+8
    const int a_row  = wm * 32 + (lane & 15);
    const int a_koff = (lane >> 4) << 3;
    //   B frags (x4 covers ntile pair): lanes 0-7 n..n+7 @k0; 8-15 same @k0+8;
    //   16-23 n+8..n+15 @k0; 24-31 @k0+8
    const int b_n    = wn * 64 + ((lane >> 4) << 3) + (lane & 7);
    const int b_koff = ((lane >> 3) & 1) << 3;

    float4 pa[4], pb[4];
#pragma unroll
    for (int i = 0; i < 4; i++) {
        pa[i] = *(const float4*)(Ab + (size_t)(lrow + 32 * i) * P + lkg * 4);
        pb[i] = *(const float4*)(Bb + (size_t)(lrow + 32 * i) * P + lkg * 4);
    }
    // store stage 0
    {
        const uint32_t st = sb;
#pragma unroll
        for (int i = 0; i < 4; i++) {
            uint32_t off = (uint32_t)((lrow + 32 * i) * ROWB + lkg * 8);
            uint32_t h0, l0, h1, l1;
            split2(pa[i].x, pa[i].y, h0, l0);
            split2(pa[i].z, pa[i].w, h1, l1);
            STS64(st + off, h0, h1);
            STS64(st + TILEB + off, l0, l1);
            split2(pb[i].x, pb[i].y, h0, l0);
            split2(pb[i].z, pb[i].w, h1, l1);
            STS64(st + 2 * TILEB + off, h0, h1);
            STS64(st + 3 * TILEB + off, l0, l1);
        }
    }
    __syncthreads();

    for (int t = 0; t < iters; ++t) {
        const uint32_t stage = sb + (uint32_t)((t & 1) * STAGEB);
        if (t + 1 < iters) {
            const int k0 = (t + 1) * BK;
#pragma unroll
            for (int i = 0; i < 4; i++) {
                pa[i] = *(const float4*)(Ab + (size_t)(lrow + 32 * i) * P + k0 + lkg * 4);
                pb[i] = *(const float4*)(Bb + (size_t)(lrow + 32 * i) * P + k0 + lkg * 4);
            }
        }
#pragma unroll
        for (int ch = 0; ch < 2; ch++) {
            uint32_t Ah[2][4], Al[2][4], Bh[8][2], Bl[8][2];
#pragma unroll
            for (int mt = 0; mt < 2; mt++) {
                uint32_t addr = stage +
                    (uint32_t)((a_row + mt * 16) * ROWB + (ch * 16 + a_koff) * 2);
                ldsm4(Ah[mt], addr);
                ldsm4(Al[mt], addr + TILEB);
            }
#pragma unroll
            for (int q = 0; q < 4; q++) {
                uint32_t addr = stage + 2 * TILEB +
                    (uint32_t)((b_n + q * 16) * ROWB + (ch * 16 + b_koff) * 2);
                uint32_t r[4];
                ldsm4(r, addr);
                Bh[q * 2][0] = r[0]; Bh[q * 2][1] = r[1];
                Bh[q * 2 + 1][0] = r[2]; Bh[q * 2 + 1][1] = r[3];
                ldsm4(r, addr + TILEB);
                Bl[q * 2][0] = r[0]; Bl[q * 2][1] = r[1];
                Bl[q * 2 + 1][0] = r[2]; Bl[q * 2 + 1][1] = r[3];
            }
#pragma unroll
            for (int mt = 0; mt < 2; mt++)
#pragma unroll
                for (int nt = 0; nt < 8; nt++) {
                    mma_bf16(acc[mt][nt], Ah[mt], Bh[nt]);
                    mma_bf16(acc[mt][nt], Ah[mt], Bl[nt]);
                    mma_bf16(acc[mt][nt], Al[mt], Bh[nt]);
                }
        }
        if (t + 1 < iters) {
            const uint32_t st = sb + (uint32_t)(((t + 1) & 1) * STAGEB);
#pragma unroll
            for (int i = 0; i < 4; i++) {
                uint32_t off = (uint32_t)((lrow + 32 * i) * ROWB + lkg * 8);
                uint32_t h0, l0, h1, l1;
                split2(pa[i].x, pa[i].y, h0, l0);
                split2(pa[i].z, pa[i].w, h1, l1);
                STS64(st + off, h0, h1);
                STS64(st + TILEB + off, l0, l1);
                split2(pb[i].x, pb[i].y, h0, l0);
                split2(pb[i].z, pb[i].w, h1, l1);
                STS64(st + 2 * TILEB + off, h0, h1);
                STS64(st + 3 * TILEB + off, l0, l1);
            }
        }
        __syncthreads();
    }

    // ----------------- epilogues -----------------
    float* smC = (float*)smraw;          // [128][129] fp32, 66048 B (overlays stages)

    if (MODE == 3) {
        float local = 0.0f;
#pragma unroll
        for (int mt = 0; mt < 2; mt++)
#pragma unroll
            for (int nt = 0; nt < 8; nt++)
#pragma unroll
                for (int i = 0; i < 4; i++)
                    local += acc[mt][nt][i] * acc[mt][nt][i];
        float bsum = blockReduceSum(local);
        if (tid == 0) atomicAdd(&g_ss, (double)bsum);
        return;
    }

    // stage accumulators to padded smem (stride 129 floats)
#pragma unroll
    for (int mt = 0; mt < 2; mt++)
#pragma unroll
        for (int nt = 0; nt < 8; nt++) {
            int r0 = wm * 32 + mt * 16 + (lane >> 2);
            int c0 = wn * 64 + nt * 8 + (lane & 3) * 2;
            smC[r0 * 129 + c0]         = acc[mt][nt][0];
            smC[r0 * 129 + c0 + 1]     = acc[mt][nt][1];
            smC[(r0 + 8) * 129 + c0]     = acc[mt][nt][2];
            smC[(r0 + 8) * 129 + c0 + 1] = acc[mt][nt][3];
        }
    __syncthreads();

    if (MODE == 1) {
        const double s = g_s;
        for (int it = 0; it < 16; it++) {
            int f = it * 256 + tid;
            int row = f >> 5, c4 = (f & 31) * 4;
            double w = (double)g_W[by * BM + row];
            double w2 = w * w;
            float sc = (float)(w2 / (s * w2 + 1.0));
            float4 v;
            v.x = smC[row * 129 + c4] * sc;
            v.y = smC[row * 129 + c4 + 1] * sc;
            v.z = smC[row * 129 + c4 + 2] * sc;
            v.w = smC[row * 129 + c4 + 3] * sc;
            size_t gi = (size_t)(by * BM + row) * P + bx * BN + c4;
            *(float4*)(O0 + gi) = v;
            if (O1) {
                O1[gi] = v.x; O1[gi + 1] = v.y; O1[gi + 2] = v.z; O1[gi + 3] = v.w;
            }
        }
    } else { // MODE 2: subtract aux, store transposed
        for (int it = 0; it < 16; it++) {
            int f = it * 256 + tid;
            int row = f >> 5, c4 = (f & 31) * 4;
            float4 sv = *(const float4*)(aux + (size_t)(by * BM + row) * P + bx * BN + c4);
            smC[row * 129 + c4]     -= sv.x;
            smC[row * 129 + c4 + 1] -= sv.y;
            smC[row * 129 + c4 + 2] -= sv.z;
            smC[row * 129 + c4 + 3] -= sv.w;
        }
        __syncthreads();
        for (int it = 0; it < 16; it++) {
            int f = it * 256 + tid;
            int n = f >> 5, m4 = (f & 31) * 4;
            float4 v;
            v.x = smC[(m4 + 0) * 129 + n];
            v.y = smC[(m4 + 1) * 129 + n];
            v.z = smC[(m4 + 2) * 129 + n];
            v.w = smC[(m4 + 3) * 129 + n];
            *(float4*)(O0 + (size_t)(bx * BN + n) * P + by * BM + m4) = v;
        }
    }
}

// ---------------- launch ---------------------------------------------------
extern "C" void kernel_launch(void* const* d_in, const int* in_sizes, int n_in,
                              void* d_out, int out_size)
{
    const float* target = (const float*)d_in[0];
    const float* source = (const float*)d_in[1];
    const float* Wb     = (const float*)d_in[2];
    float* out = (float*)d_out;

    int P = (int)(sqrt((double)in_sizes[0]) + 0.5);
    size_t pp = (size_t)P * P;

    bool has_matrix = (size_t)out_size >= pp;
    bool has_loss   = ((size_t)out_size != pp);
    float* outW = has_matrix ? (out + (out_size - (int)pp)) : nullptr;

    float* wm  = nullptr; cudaGetSymbolAddress((void**)&wm,  g_Wm);
    float* prT = nullptr; cudaGetSymbolAddress((void**)&prT, g_PrT);
    float* tt  = nullptr; cudaGetSymbolAddress((void**)&tt,  g_Tt);

    cudaFuncSetAttribute(gemm_mma<1>, cudaFuncAttributeMaxDynamicSharedMemorySize, SMEM_SZ);
    cudaFuncSetAttribute(gemm_mma<2>, cudaFuncAttributeMaxDynamicSharedMemorySize, SMEM_SZ);
    cudaFuncSetAttribute(gemm_mma<3>, cudaFuncAttributeMaxDynamicSharedMemorySize, SMEM_SZ);

    init_kernel<<<1, 1>>>();
    sumsq_kernel<<<2048, 256>>>(target, pp);
    rowsum_kernel<<<P, 256>>>(Wb, P);
    transpose_kernel<<<dim3(P / 32, P / 32), dim3(32, 8)>>>(target, tt, P);

    dim3 grid(P / BN, P / BM);
    // Wm = scale .* (source @ target^T)
    gemm_mma<1><<<grid, 256, SMEM_SZ>>>(source, target, nullptr, wm, outW, P);
    // primary^T = (Wm @ target - source)^T
    gemm_mma<2><<<grid, 256, SMEM_SZ>>>(wm, tt, source, prT, nullptr, P);
    // ss += ||W_beta @ primary||^2
    gemm_mma<3><<<grid, 256, SMEM_SZ>>>(Wb, prT, nullptr, nullptr, nullptr, P);

    if (has_loss) finalize_kernel<<<1, 1>>>(out);
}